// round 1
// baseline (speedup 1.0000x reference)
#include <cuda_runtime.h>
#include <math_constants.h>
#include <cstdint>

#define NNODES 2048
#define HID    1024
#define TSTEPS (NNODES + NNODES / 8)   // 2304
#define LDB_B  1028                    // padded leading dim for B (keeps float4 alignment)

// -------- scratch (device globals; no allocation allowed) --------
__device__ float g_K [NNODES * HID];          // K = node_emb @ Wk^T + bk        [2048,1024]
__device__ float g_WqT[(HID + 2) * HID];      // Wq^T                            [1026,1024]
__device__ float g_B [NNODES * LDB_B];        // B = K @ Wq                      [2048,1026] (ld 1028)
__device__ float g_ST[(size_t)NNODES * NNODES]; // ST[l][k] = node_emb[l] . B[k,:H]  [2048,2048]
__device__ float g_u [NNODES];                // B[:,H]   (load/cap coefficient)
__device__ float g_w0[NNODES];                // K @ bq

// ---------------------------------------------------------------------------
// Tiled fp32 GEMM (NT form): C[M,N] = A[M,K] * Bt[N,K]^T (+ bias[N])
// A row-major (lda), Bt row-major (ldb), C row-major (ldc).
// Requires: M % 128 == 0, K % 8 == 0, A/Bt rows 16B-aligned. N guarded.
// ---------------------------------------------------------------------------
__global__ __launch_bounds__(256) void sgemm_nt(
    const float* __restrict__ A, int lda,
    const float* __restrict__ Bt, int ldb,
    float* __restrict__ C, int ldc,
    int M, int N, int K, const float* __restrict__ bias)
{
    __shared__ float As[8][132];
    __shared__ float Bs[8][132];

    const int tid = threadIdx.x;
    const int tx = tid % 16;          // N direction (8 cols each)
    const int ty = tid / 16;          // M direction (8 rows each)
    const int m0 = blockIdx.y * 128;
    const int n0 = blockIdx.x * 128;

    const int lrow = tid >> 1;        // 0..127
    const int lk4  = (tid & 1) * 4;   // 0 or 4

    float acc[8][8];
#pragma unroll
    for (int i = 0; i < 8; i++)
#pragma unroll
        for (int j = 0; j < 8; j++) acc[i][j] = 0.0f;

    for (int k0 = 0; k0 < K; k0 += 8) {
        float4 av = *(const float4*)(A + (size_t)(m0 + lrow) * lda + k0 + lk4);
        As[lk4 + 0][lrow] = av.x; As[lk4 + 1][lrow] = av.y;
        As[lk4 + 2][lrow] = av.z; As[lk4 + 3][lrow] = av.w;

        float4 bv = make_float4(0.f, 0.f, 0.f, 0.f);
        const int brow = n0 + lrow;
        if (brow < N)
            bv = *(const float4*)(Bt + (size_t)brow * ldb + k0 + lk4);
        Bs[lk4 + 0][lrow] = bv.x; Bs[lk4 + 1][lrow] = bv.y;
        Bs[lk4 + 2][lrow] = bv.z; Bs[lk4 + 3][lrow] = bv.w;

        __syncthreads();

#pragma unroll
        for (int kk = 0; kk < 8; kk++) {
            float4 a0 = *(const float4*)&As[kk][ty * 8];
            float4 a1 = *(const float4*)&As[kk][ty * 8 + 4];
            float4 b0 = *(const float4*)&Bs[kk][tx * 8];
            float4 b1 = *(const float4*)&Bs[kk][tx * 8 + 4];
            float a[8] = {a0.x, a0.y, a0.z, a0.w, a1.x, a1.y, a1.z, a1.w};
            float b[8] = {b0.x, b0.y, b0.z, b0.w, b1.x, b1.y, b1.z, b1.w};
#pragma unroll
            for (int i = 0; i < 8; i++)
#pragma unroll
                for (int j = 0; j < 8; j++)
                    acc[i][j] = fmaf(a[i], b[j], acc[i][j]);
        }
        __syncthreads();
    }

#pragma unroll
    for (int i = 0; i < 8; i++) {
        const int r = m0 + ty * 8 + i;
#pragma unroll
        for (int j = 0; j < 8; j++) {
            const int c = n0 + tx * 8 + j;
            if (c < N) {
                float v = acc[i][j];
                if (bias) v += bias[c];
                C[(size_t)r * ldc + c] = v;
            }
        }
    }
}

// ---------------------------------------------------------------------------
// 32x32 tiled transpose: out[C][R] = in[R][C]^T
// ---------------------------------------------------------------------------
__global__ void transpose_kernel(const float* __restrict__ in, float* __restrict__ out,
                                 int R, int C)
{
    __shared__ float t[32][33];
    int c = blockIdx.x * 32 + threadIdx.x;
    int r = blockIdx.y * 32 + threadIdx.y;
    if (r < R && c < C) t[threadIdx.y][threadIdx.x] = in[(size_t)r * C + c];
    __syncthreads();
    int oc   = blockIdx.y * 32 + threadIdx.x;  // output col = original row
    int orow = blockIdx.x * 32 + threadIdx.y;  // output row = original col
    if (orow < C && oc < R) out[(size_t)orow * R + oc] = t[threadIdx.x][threadIdx.y];
}

// ---------------------------------------------------------------------------
// u[k] = B[k, HID];  w0[k] = K[k,:] . bq   (one warp per k)
// ---------------------------------------------------------------------------
__global__ void uw_kernel(const float* __restrict__ bq)
{
    int k = blockIdx.x * 8 + (threadIdx.x >> 5);
    int lane = threadIdx.x & 31;
    if (k >= NNODES) return;
    float s = 0.0f;
    const float* krow = g_K + (size_t)k * HID;
    for (int j = lane; j < HID; j += 32) s = fmaf(krow[j], bq[j], s);
#pragma unroll
    for (int o = 16; o > 0; o >>= 1) s += __shfl_down_sync(0xffffffffu, s, o);
    if (lane == 0) {
        g_w0[k] = s;
        g_u[k]  = g_B[(size_t)k * LDB_B + HID];
    }
}

// ---------------------------------------------------------------------------
// Sequential greedy decode. Single CTA, 1024 threads, 2 nodes per thread.
// Output (float32): out[0..TSTEPS] = tour, out[TSTEPS+1 .. 2*TSTEPS] = scores.
// ---------------------------------------------------------------------------
__global__ __launch_bounds__(1024) void decode_kernel(
    const float* __restrict__ demands,
    const int* __restrict__ cap_p,
    const int* __restrict__ depot_p,
    float* __restrict__ out)
{
    __shared__ unsigned char vis[NNODES];
    __shared__ float dem[NNODES];
    __shared__ float wvs[32];
    __shared__ int   wis[32];

    const int tid  = threadIdx.x;
    const int lane = tid & 31;
    const int wid  = tid >> 5;

    const float capf  = (float)(*cap_p);
    const int   depot = *depot_p;
    const float SC    = 0.015625f;   // ALPHA * 1/sqrt(HID) = 0.5/32 (exact pow2)

    dem[2 * tid]     = demands[2 * tid];
    dem[2 * tid + 1] = demands[2 * tid + 1];
    vis[2 * tid] = 0; vis[2 * tid + 1] = 0;
    __syncthreads();
    if (tid == 0) { vis[depot] = 1; out[0] = (float)depot; }
    __syncthreads();

    const float d0 = dem[2 * tid];
    const float d1 = dem[2 * tid + 1];
    const float2 uv  = ((const float2*)g_u)[tid];
    const float2 w0v = ((const float2*)g_w0)[tid];

    float loadv = capf;
    int   last  = depot;
    int   done  = 0;
    int   vcount = 1;               // depot pre-visited

    for (int step = 0; step < TSTEPS; step++) {
        const float2 v = ((const float2*)(g_ST + (size_t)last * NNODES))[tid];
        const float lf = loadv / capf;
        const float s0 = (v.x + uv.x * lf + w0v.x) * SC;
        const float s1 = (v.y + uv.y * lf + w0v.y) * SC;

        float m0 = (!vis[2 * tid]     && d0 <= loadv) ? s0 : -CUDART_INF_F;
        float m1 = (!vis[2 * tid + 1] && d1 <= loadv) ? s1 : -CUDART_INF_F;

        float bv; int bi;
        if (m1 > m0) { bv = m1; bi = 2 * tid + 1; }
        else         { bv = m0; bi = 2 * tid; }

#pragma unroll
        for (int o = 16; o > 0; o >>= 1) {
            float ov = __shfl_down_sync(0xffffffffu, bv, o);
            int   oi = __shfl_down_sync(0xffffffffu, bi, o);
            if (ov > bv || (ov == bv && oi < bi)) { bv = ov; bi = oi; }
        }
        if (lane == 0) { wvs[wid] = bv; wis[wid] = bi; }
        __syncthreads();

        bv = wvs[lane]; bi = wis[lane];     // every warp reduces the 32 partials
#pragma unroll
        for (int o = 16; o > 0; o >>= 1) {
            float ov = __shfl_down_sync(0xffffffffu, bv, o);
            int   oi = __shfl_down_sync(0xffffffffu, bi, o);
            if (ov > bv || (ov == bv && oi < bi)) { bv = ov; bi = oi; }
        }
        bv = __shfl_sync(0xffffffffu, bv, 0);
        bi = __shfl_sync(0xffffffffu, bi, 0);

        const int has  = (bv != -CUDART_INF_F);
        const int take = has && !done;
        const int nxt  = take ? bi : depot;

        if (tid == 0) {
            out[1 + step]            = (float)nxt;
            out[(TSTEPS + 1) + step] = take ? bv : 0.0f;
        }

        if (take) {
            if (bi == 2 * tid)          vis[2 * tid] = 1;
            else if (bi == 2 * tid + 1) vis[2 * tid + 1] = 1;
            loadv = loadv - dem[bi];
            vcount++;
        } else {
            loadv = capf;
        }
        done = done || (!take && vcount == NNODES);
        last = nxt;
        __syncthreads();
    }
}

// ---------------------------------------------------------------------------
extern "C" void kernel_launch(void* const* d_in, const int* in_sizes, int n_in,
                              void* d_out, int out_size)
{
    const float* node_emb = (const float*)d_in[0];   // [2048,1024]
    const float* demands  = (const float*)d_in[1];   // [2048]
    const float* Wq       = (const float*)d_in[2];   // [1024,1026]
    const float* bq       = (const float*)d_in[3];   // [1024]
    const float* Wk       = (const float*)d_in[4];   // [1024,1024]
    const float* bk       = (const float*)d_in[5];   // [1024]
    const int*   cap_p    = (const int*)d_in[6];     // scalar 40
    const int*   depot_p  = (const int*)d_in[7];     // scalar 0
    float* out = (float*)d_out;

    void *pK, *pWqT, *pB, *pST;
    cudaGetSymbolAddress(&pK,  g_K);
    cudaGetSymbolAddress(&pWqT, g_WqT);
    cudaGetSymbolAddress(&pB,  g_B);
    cudaGetSymbolAddress(&pST, g_ST);

    // 1) K = node_emb @ Wk^T + bk
    sgemm_nt<<<dim3(HID / 128, NNODES / 128), 256>>>(
        node_emb, HID, Wk, HID, (float*)pK, HID, NNODES, HID, HID, bk);

    // 2) WqT = Wq^T                      (Wq: [1024,1026] -> WqT: [1026,1024])
    transpose_kernel<<<dim3((HID + 2 + 31) / 32, (HID + 31) / 32), dim3(32, 32)>>>(
        Wq, (float*)pWqT, HID, HID + 2);

    // 3) B = K @ Wq                      ([2048,1026], ld 1028)
    sgemm_nt<<<dim3((HID + 2 + 127) / 128, NNODES / 128), 256>>>(
        (const float*)pK, HID, (const float*)pWqT, HID,
        (float*)pB, LDB_B, NNODES, HID + 2, HID, nullptr);

    // 4) ST = node_emb @ B[:, :HID]^T    ([2048,2048])
    sgemm_nt<<<dim3(NNODES / 128, NNODES / 128), 256>>>(
        node_emb, HID, (const float*)pB, LDB_B,
        (float*)pST, NNODES, NNODES, NNODES, HID, nullptr);

    // 5) u, w0
    uw_kernel<<<NNODES / 8, 256>>>(bq);

    // 6) sequential decode
    decode_kernel<<<1, 1024>>>(demands, cap_p, depot_p, out);
}

// round 3
// speedup vs baseline: 1.2512x; 1.2512x over previous
#include <cuda_runtime.h>
#include <math_constants.h>
#include <cstdint>

#define NNODES 2048
#define HID    1024
#define TSTEPS (NNODES + NNODES / 8)   // 2304
#define LDB_B  1028                    // padded leading dim for B (keeps float4 alignment)

// -------- scratch (device globals; no allocation allowed) --------
__device__ __align__(16) float g_K [NNODES * HID];          // K = node_emb @ Wk^T + bk   [2048,1024]
__device__ __align__(16) float g_WqT[(HID + 2) * HID];      // Wq^T                       [1026,1024]
__device__ __align__(16) float g_B [NNODES * LDB_B];        // B = K @ Wq                 [2048,1026]
__device__ __align__(16) float g_ST[(size_t)NNODES * NNODES]; // ST'[l][k] = SC*(emb[l].B[k,:H] + w0[k])
__device__ __align__(16) float g_u [NNODES];                // u'[k] = SC * B[k,HID]
__device__ __align__(16) float g_w0[NNODES];                // w0[k] = K[k,:] . bq

// ---------------------------------------------------------------------------
// Tiled fp32 GEMM (NT form): C[M,N] = scale * (A[M,K] * Bt[N,K]^T + bias[N])
// A row-major (lda), Bt row-major (ldb), C row-major (ldc).
// Requires: M % 128 == 0, K % 8 == 0, rows 16B-aligned. N guarded.
// ---------------------------------------------------------------------------
__global__ __launch_bounds__(256) void sgemm_nt(
    const float* __restrict__ A, int lda,
    const float* __restrict__ Bt, int ldb,
    float* __restrict__ C, int ldc,
    int M, int N, int K, const float* __restrict__ bias, float scale)
{
    __shared__ float As[8][132];
    __shared__ float Bs[8][132];

    const int tid = threadIdx.x;
    const int tx = tid % 16;          // N direction (8 cols each)
    const int ty = tid / 16;          // M direction (8 rows each)
    const int m0 = blockIdx.y * 128;
    const int n0 = blockIdx.x * 128;

    const int lrow = tid >> 1;        // 0..127
    const int lk4  = (tid & 1) * 4;   // 0 or 4

    float acc[8][8];
#pragma unroll
    for (int i = 0; i < 8; i++)
#pragma unroll
        for (int j = 0; j < 8; j++) acc[i][j] = 0.0f;

    for (int k0 = 0; k0 < K; k0 += 8) {
        float4 av = *(const float4*)(A + (size_t)(m0 + lrow) * lda + k0 + lk4);
        As[lk4 + 0][lrow] = av.x; As[lk4 + 1][lrow] = av.y;
        As[lk4 + 2][lrow] = av.z; As[lk4 + 3][lrow] = av.w;

        float4 bv = make_float4(0.f, 0.f, 0.f, 0.f);
        const int brow = n0 + lrow;
        if (brow < N)
            bv = *(const float4*)(Bt + (size_t)brow * ldb + k0 + lk4);
        Bs[lk4 + 0][lrow] = bv.x; Bs[lk4 + 1][lrow] = bv.y;
        Bs[lk4 + 2][lrow] = bv.z; Bs[lk4 + 3][lrow] = bv.w;

        __syncthreads();

#pragma unroll
        for (int kk = 0; kk < 8; kk++) {
            float4 a0 = *(const float4*)&As[kk][ty * 8];
            float4 a1 = *(const float4*)&As[kk][ty * 8 + 4];
            float4 b0 = *(const float4*)&Bs[kk][tx * 8];
            float4 b1 = *(const float4*)&Bs[kk][tx * 8 + 4];
            float a[8] = {a0.x, a0.y, a0.z, a0.w, a1.x, a1.y, a1.z, a1.w};
            float b[8] = {b0.x, b0.y, b0.z, b0.w, b1.x, b1.y, b1.z, b1.w};
#pragma unroll
            for (int i = 0; i < 8; i++)
#pragma unroll
                for (int j = 0; j < 8; j++)
                    acc[i][j] = fmaf(a[i], b[j], acc[i][j]);
        }
        __syncthreads();
    }

#pragma unroll
    for (int i = 0; i < 8; i++) {
        const int r = m0 + ty * 8 + i;
#pragma unroll
        for (int j = 0; j < 8; j++) {
            const int c = n0 + tx * 8 + j;
            if (c < N) {
                float v = acc[i][j];
                if (bias) v += bias[c];
                C[(size_t)r * ldc + c] = v * scale;
            }
        }
    }
}

// ---------------------------------------------------------------------------
// 32x32 tiled transpose: out[C][R] = in[R][C]^T
// ---------------------------------------------------------------------------
__global__ void transpose_kernel(const float* __restrict__ in, float* __restrict__ out,
                                 int R, int C)
{
    __shared__ float t[32][33];
    int c = blockIdx.x * 32 + threadIdx.x;
    int r = blockIdx.y * 32 + threadIdx.y;
    if (r < R && c < C) t[threadIdx.y][threadIdx.x] = in[(size_t)r * C + c];
    __syncthreads();
    int oc   = blockIdx.y * 32 + threadIdx.x;  // output col = original row
    int orow = blockIdx.x * 32 + threadIdx.y;  // output row = original col
    if (orow < C && oc < R) out[(size_t)orow * R + oc] = t[threadIdx.x][threadIdx.y];
}

// ---------------------------------------------------------------------------
// w0[k] = K[k,:] . bq ; u'[k] = SC * B[k, HID]   (one warp per k)
// ---------------------------------------------------------------------------
__global__ void uw_kernel(const float* __restrict__ bq)
{
    const float SC = 0.015625f;  // ALPHA / sqrt(HID) = 0.5/32 (exact pow2)
    int k = blockIdx.x * 8 + (threadIdx.x >> 5);
    int lane = threadIdx.x & 31;
    if (k >= NNODES) return;
    float s = 0.0f;
    const float* krow = g_K + (size_t)k * HID;
    for (int j = lane; j < HID; j += 32) s = fmaf(krow[j], bq[j], s);
#pragma unroll
    for (int o = 16; o > 0; o >>= 1) s += __shfl_down_sync(0xffffffffu, s, o);
    if (lane == 0) {
        g_w0[k] = s;
        g_u[k]  = g_B[(size_t)k * LDB_B + HID] * SC;
    }
}

// ---------------------------------------------------------------------------
// Sequential greedy decode. Single CTA, 128 threads (4 warps), 16 nodes/thread.
// Per node k: score = ST'[last][k] + u'[k] * (load/cap)   (SC and w0 prefolded)
// Output (float32): out[0..TSTEPS] = tour, out[TSTEPS+1 .. 2*TSTEPS] = scores.
// ---------------------------------------------------------------------------
__global__ __launch_bounds__(128) void decode_kernel(
    const float* __restrict__ demands,
    const int* __restrict__ cap_p,
    const int* __restrict__ depot_p,
    float* __restrict__ out)
{
    __shared__ __align__(16) float dem_s[NNODES];
    __shared__ float wv[4];
    __shared__ int   wi[4];

    const int t    = threadIdx.x;      // 0..127
    const int lane = t & 31;
    const int wid  = t >> 5;

    const float capf  = (float)(*cap_p);
    const int   depot = *depot_p;

    // demands -> smem (for the scalar load-update lookup)
    for (int i = t; i < NNODES / 4; i += 128)
        ((float4*)dem_s)[i] = ((const float4*)demands)[i];

    // per-thread register copies: u' and demands for this thread's 16 nodes
    // thread owns elements k = (i*128 + t)*4 + c,  i in 0..3, c in 0..3
    float4 u4[4];
#pragma unroll
    for (int i = 0; i < 4; i++)
        u4[i] = ((const float4*)g_u)[i * 128 + t];
    __syncthreads();
    float4 dm4[4];
#pragma unroll
    for (int i = 0; i < 4; i++)
        dm4[i] = ((const float4*)dem_s)[i * 128 + t];

    unsigned vis = 0;                  // bit (i*4+c) = visited(node (i*128+t)*4+c)
    if (((depot >> 2) & 127) == t) vis |= 1u << (((depot >> 9) << 2) + (depot & 3));
    if (t == 0) out[0] = (float)depot;

    float loadv  = capf;
    int   last   = depot;
    int   done   = 0;
    int   vcount = 1;                  // depot pre-visited

    for (int step = 0; step < TSTEPS; step++) {
        const float4* row = (const float4*)(g_ST + (size_t)last * NNODES);
        float4 st[4];
#pragma unroll
        for (int i = 0; i < 4; i++) st[i] = row[i * 128 + t];

        const float lf = loadv / capf;

        float bv = -CUDART_INF_F;
        int   bi = 0x7fffffff;
#pragma unroll
        for (int i = 0; i < 4; i++) {
            const float* sp = (const float*)&st[i];
            const float* up = (const float*)&u4[i];
            const float* dp = (const float*)&dm4[i];
#pragma unroll
            for (int c = 0; c < 4; c++) {
                float s = fmaf(up[c], lf, sp[c]);
                bool feas = (((vis >> (i * 4 + c)) & 1u) == 0u) && (dp[c] <= loadv);
                float m = feas ? s : -CUDART_INF_F;
                int  k = ((i * 128 + t) << 2) + c;
                if (m > bv || (m == bv && k < bi)) { bv = m; bi = k; }
            }
        }

        // warp reduce (tie -> lowest index)
#pragma unroll
        for (int o = 16; o > 0; o >>= 1) {
            float ov = __shfl_down_sync(0xffffffffu, bv, o);
            int   oi = __shfl_down_sync(0xffffffffu, bi, o);
            if (ov > bv || (ov == bv && oi < bi)) { bv = ov; bi = oi; }
        }
        if (lane == 0) { wv[wid] = bv; wi[wid] = bi; }
        __syncthreads();

        // every thread reduces the 4 warp partials (smem broadcast reads)
        bv = wv[0]; bi = wi[0];
#pragma unroll
        for (int w = 1; w < 4; w++) {
            float ov = wv[w]; int oi = wi[w];
            if (ov > bv || (ov == bv && oi < bi)) { bv = ov; bi = oi; }
        }

        const int has  = (bv != -CUDART_INF_F);
        const int take = has && !done;
        const int nxt  = take ? bi : depot;

        if (t == 0) {
            out[1 + step]            = (float)nxt;
            out[(TSTEPS + 1) + step] = take ? bv : 0.0f;
        }

        if (take) {
            if (((bi >> 2) & 127) == t) vis |= 1u << (((bi >> 9) << 2) + (bi & 3));
            loadv = loadv - dem_s[bi];
            vcount++;
        } else {
            loadv = capf;
        }
        done = done || (!take && vcount == NNODES);
        last = nxt;
        __syncthreads();   // WAR: wv/wi reused next step
    }
}

// ---------------------------------------------------------------------------
extern "C" void kernel_launch(void* const* d_in, const int* in_sizes, int n_in,
                              void* d_out, int out_size)
{
    const float* node_emb = (const float*)d_in[0];   // [2048,1024]
    const float* demands  = (const float*)d_in[1];   // [2048]
    const float* Wq       = (const float*)d_in[2];   // [1024,1026]
    const float* bq       = (const float*)d_in[3];   // [1024]
    const float* Wk       = (const float*)d_in[4];   // [1024,1024]
    const float* bk       = (const float*)d_in[5];   // [1024]
    const int*   cap_p    = (const int*)d_in[6];     // scalar 40
    const int*   depot_p  = (const int*)d_in[7];     // scalar 0
    float* out = (float*)d_out;

    const float SC = 0.015625f;  // ALPHA / sqrt(HID)

    void *pK, *pWqT, *pB, *pST, *pW0;
    cudaGetSymbolAddress(&pK,   g_K);
    cudaGetSymbolAddress(&pWqT, g_WqT);
    cudaGetSymbolAddress(&pB,   g_B);
    cudaGetSymbolAddress(&pST,  g_ST);
    cudaGetSymbolAddress(&pW0,  g_w0);

    // 1) K = node_emb @ Wk^T + bk
    sgemm_nt<<<dim3(HID / 128, NNODES / 128), 256>>>(
        node_emb, HID, Wk, HID, (float*)pK, HID, NNODES, HID, HID, bk, 1.0f);

    // 2) WqT = Wq^T                      (Wq: [1024,1026] -> WqT: [1026,1024])
    transpose_kernel<<<dim3((HID + 2 + 31) / 32, (HID + 31) / 32), dim3(32, 32)>>>(
        Wq, (float*)pWqT, HID, HID + 2);

    // 3) B = K @ Wq                      ([2048,1026], ld 1028)
    sgemm_nt<<<dim3((HID + 2 + 127) / 128, NNODES / 128), 256>>>(
        (const float*)pK, HID, (const float*)pWqT, HID,
        (float*)pB, LDB_B, NNODES, HID + 2, HID, nullptr, 1.0f);

    // 4) w0 = K @ bq ; u' = SC * B[:,HID]   (must precede GEMM that folds w0)
    uw_kernel<<<NNODES / 8, 256>>>(bq);

    // 5) ST' = SC * (node_emb @ B[:, :HID]^T + w0)    ([2048,2048])
    sgemm_nt<<<dim3(NNODES / 128, NNODES / 128), 256>>>(
        node_emb, HID, (const float*)pB, LDB_B,
        (float*)pST, NNODES, NNODES, NNODES, HID, (const float*)pW0, SC);

    // 6) sequential decode (single CTA, 4 warps)
    decode_kernel<<<1, 128>>>(demands, cap_p, depot_p, out);
}